// round 4
// baseline (speedup 1.0000x reference)
#include <cuda_runtime.h>
#include <cstdint>
#include <cstddef>

using ull = unsigned long long;

#define NROWS   32          // rows per CTA
#define XS_BUF  10496       // floats: 32 rows * (64*5+8) worst case
#define WS_BUF  1024        // floats: 64 mi * 16 o
#define SMEM_FLOATS (2*XS_BUF + 2*WS_BUF)
#define SMEM_BYTES  (SMEM_FLOATS * 4)

__device__ __forceinline__ void cpa16(float* dst, const float* src) {
    unsigned d = (unsigned)__cvta_generic_to_shared(dst);
    asm volatile("cp.async.cg.shared.global [%0], [%1], 16;" :: "r"(d), "l"(src));
}
__device__ __forceinline__ ull pack2(float a) {
    ull r; asm("mov.b64 %0, {%1, %1};" : "=l"(r) : "f"(a)); return r;
}
__device__ __forceinline__ void ffma2(ull& acc, ull a, ull b) {
    asm("fma.rn.f32x2 %0, %1, %2, %0;" : "+l"(acc) : "l"(a), "l"(b));
}

// Stage one (l, c) chunk: x[32 rows][64*d floats] (+8-float row pad) and w_l[c*64:(c+1)*64, :16]
__device__ __forceinline__ void stage_chunk(const float* __restrict__ x,
                                            const float* __restrict__ wl,
                                            int n0, int c, int off, int d,
                                            float* xs, float* ws, int tid)
{
    const int stride = 64 * d + 8;
    const int row = tid >> 3, l8 = tid & 7;
    const float* gr = x + (size_t)(n0 + row) * 9216 + c * 576 + off;
    float* sr = xs + row * stride;
    // 16*d float4 per row, 8 threads per row -> 2*d each; warp covers 4 rows x 128B contiguous
    for (int k = 0; k < 2 * d; k++) {
        int v4 = (l8 + 8 * k) * 4;
        cpa16(sr + v4, gr + v4);
    }
    // weights: 64*16 floats = 256 float4, one per thread
    cpa16(ws + tid * 4, wl + c * 1024 + tid * 4);
    asm volatile("cp.async.commit_group;" ::: "memory");
}

// Compute one chunk. D = irrep dim, DOFF = output dim offset (0/1/4).
// acc[dd] is f32x2 over the output-channel pair (2j, 2j+1).
template<int D, int DOFF>
__device__ __forceinline__ void compute_chunk(const float* __restrict__ xs,
                                              const float* __restrict__ ws,
                                              ull acc[9], int r, int j)
{
    const float* xr = xs + r * (64 * D + 8);
    const float* wj = ws + 2 * j;
#pragma unroll 4
    for (int g = 0; g < 16; g++) {            // 4 multiplicities per group
        ull w4[4];
#pragma unroll
        for (int u = 0; u < 4; u++)
            w4[u] = *(const ull*)(wj + (4 * g + u) * 16);   // broadcast LDS.64
#pragma unroll
        for (int v = 0; v < D; v++) {         // aligned float4 walk of 4*D floats
            float4 a = *(const float4*)(xr + g * 4 * D + 4 * v);
            float av0 = a.x, av1 = a.y, av2 = a.z, av3 = a.w;
            { int e = 4 * v + 0; ffma2(acc[DOFF + e % D], pack2(av0), w4[e / D]); }
            { int e = 4 * v + 1; ffma2(acc[DOFF + e % D], pack2(av1), w4[e / D]); }
            { int e = 4 * v + 2; ffma2(acc[DOFF + e % D], pack2(av2), w4[e / D]); }
            { int e = 4 * v + 3; ffma2(acc[DOFF + e % D], pack2(av3), w4[e / D]); }
        }
    }
}

__global__ void __launch_bounds__(256, 2)
GeneralLinear_841813590622_kernel(const float* __restrict__ x,
                                  const float* __restrict__ w0,
                                  const float* __restrict__ w1,
                                  const float* __restrict__ w2,
                                  float* __restrict__ out)
{
    extern __shared__ float smem[];
    float* xsb[2] = { smem, smem + XS_BUF };
    float* wsb[2] = { smem + 2 * XS_BUF, smem + 2 * XS_BUF + WS_BUF };
    const float* wl[3] = { w0, w1, w2 };
    const int offs[3] = { 0, 64, 256 };
    const int dims[3] = { 1, 3, 5 };

    const int tid = threadIdx.x;
    const int n0 = blockIdx.x * NROWS;
    const int r = tid >> 3, j = tid & 7;

    ull acc[9];
#pragma unroll
    for (int q = 0; q < 9; q++) acc[q] = 0ull;

    stage_chunk(x, wl[0], n0, 0, offs[0], dims[0], xsb[0], wsb[0], tid);

    for (int i = 0; i < 48; i++) {
        const int b = i & 1;
        const int nx = i + 1;
        if (nx < 48) {
            const int ln = nx >> 4, cn = nx & 15;
            stage_chunk(x, wl[ln], n0, cn, offs[ln], dims[ln], xsb[nx & 1], wsb[nx & 1], tid);
            asm volatile("cp.async.wait_group 1;" ::: "memory");
        } else {
            asm volatile("cp.async.wait_group 0;" ::: "memory");
        }
        __syncthreads();

        const int l = i >> 4;
        if (l == 0)      compute_chunk<1, 0>(xsb[b], wsb[b], acc, r, j);
        else if (l == 1) compute_chunk<3, 1>(xsb[b], wsb[b], acc, r, j);
        else             compute_chunk<5, 4>(xsb[b], wsb[b], acc, r, j);
        __syncthreads();   // protect buffer b before it is restaged next iteration
    }

    // epilogue: out[n, o, dd], scale 1/sqrt(1024) = 1/32
    const float s = 0.03125f;
    float* o0 = out + ((size_t)(n0 + r) * 16 + 2 * j) * 9;
#pragma unroll
    for (int dd = 0; dd < 9; dd++) {
        float lo, hi;
        asm("mov.b64 {%0, %1}, %2;" : "=f"(lo), "=f"(hi) : "l"(acc[dd]));
        o0[dd]     = lo * s;
        o0[9 + dd] = hi * s;
    }
}

extern "C" void kernel_launch(void* const* d_in, const int* in_sizes, int n_in,
                              void* d_out, int out_size)
{
    const float* x  = (const float*)d_in[0];
    const float* w0 = (const float*)d_in[1];
    const float* w1 = (const float*)d_in[2];
    const float* w2 = (const float*)d_in[3];
    float* out = (float*)d_out;

    cudaFuncSetAttribute(GeneralLinear_841813590622_kernel,
                         cudaFuncAttributeMaxDynamicSharedMemorySize, SMEM_BYTES);
    GeneralLinear_841813590622_kernel<<<256, 256, SMEM_BYTES>>>(x, w0, w1, w2, out);
}

// round 7
// speedup vs baseline: 1.1493x; 1.1493x over previous
#include <cuda_runtime.h>
#include <cstdint>
#include <cstddef>

using ull = unsigned long long;

#define NROWS   32                    // rows per CTA
#define XS_BUF  10368                 // floats: 32 rows * (64*5+4) worst case (l=2)
#define WS_BUF  1280                  // floats: 64 w-rows * 20 (padded, permuted)
#define SMEM_FLOATS (2*XS_BUF + 2*WS_BUF)
#define SMEM_BYTES  (SMEM_FLOATS * 4)  // 93184 B

__device__ __forceinline__ void cpa16(float* dst, const float* src) {
    unsigned d = (unsigned)__cvta_generic_to_shared(dst);
    asm volatile("cp.async.cg.shared.global [%0], [%1], 16;" :: "r"(d), "l"(src));
}
__device__ __forceinline__ ull pack2(float a) {
    ull r; asm("mov.b64 %0, {%1, %1};" : "=l"(r) : "f"(a)); return r;
}
__device__ __forceinline__ void ffma2(ull& acc, ull a, ull b) {
    asm("fma.rn.f32x2 %0, %1, %2, %0;" : "+l"(acc) : "l"(a), "l"(b));
}
__device__ __forceinline__ ull addf2(ull a, ull b) {
    ull r; asm("add.rn.f32x2 %0, %1, %2;" : "=l"(r) : "l"(a), "l"(b)); return r;
}

// Stage one (l, c) chunk.
// x rows: 64*d floats each, smem row stride 64*d+4 (bank spread).
// weights: 64 rows x 16 floats; smem row m' = perm(m) = (m%8)*8 + m/8, stride 20 floats
// so that in compute, thread kg reading row (u*8+kg) hits all 8 bank-quads (20*kg mod 32 distinct).
__device__ __forceinline__ void stage_chunk(const float* __restrict__ x,
                                            const float* __restrict__ wl,
                                            int n0, int c, int off, int d,
                                            float* xs, float* ws, int tid)
{
    const int stride = 64 * d + 4;
    const int row = tid >> 3, l8 = tid & 7;
    const float* gr = x + (size_t)(n0 + row) * 9216 + c * 576 + off;
    float* sr = xs + row * stride;
    // 16*d float4 per row, 8 threads per row -> 2*d each; coalesced 128B per 8 lanes
    for (int k = 0; k < 2 * d; k++) {
        int v4 = (l8 + 8 * k) * 4;
        cpa16(sr + v4, gr + v4);
    }
    // weights: 256 float4, one per thread; permuted destination
    const int m = tid >> 2, q = tid & 3;
    const int pm = (m & 7) * 8 + (m >> 3);
    cpa16(ws + pm * 20 + q * 4, wl + c * 1024 + tid * 4);
    asm volatile("cp.async.commit_group;" ::: "memory");
}

// Compute one chunk. D = irrep dim (1/3/5), DOFF = dim offset in acc (0/1/4).
// Thread (r, kg) owns multiplicities [kg*8, kg*8+8), all 16 outputs as 8 f32x2 pairs.
template<int D, int DOFF>
__device__ __forceinline__ void compute_chunk(const float* __restrict__ xs,
                                              const float* __restrict__ ws,
                                              ull (&acc)[8][9], int r, int kg)
{
    const float* xr = xs + r * (64 * D + 4) + kg * (8 * D);
#pragma unroll
    for (int h = 0; h < 2; h++) {                    // two halves of 4 multiplicities
        float xh[4 * D];
        const float4* xp = (const float4*)(xr + h * (4 * D));
#pragma unroll
        for (int v = 0; v < D; v++) {
            float4 t = xp[v];
            xh[4*v] = t.x; xh[4*v+1] = t.y; xh[4*v+2] = t.z; xh[4*v+3] = t.w;
        }
#pragma unroll
        for (int u4 = 0; u4 < 4; u4++) {
            const int u = h * 4 + u4;                // mi-local 0..7
            const ulonglong2* wp = (const ulonglong2*)(ws + (u * 8 + kg) * 20);
            ull w8[8];
#pragma unroll
            for (int q = 0; q < 4; q++) {            // 4x LDS.128, conflict-free
                ulonglong2 wv = wp[q];
                w8[2*q] = wv.x; w8[2*q+1] = wv.y;
            }
#pragma unroll
            for (int d = 0; d < D; d++) {
                ull av = pack2(xh[u4 * D + d]);      // 1 pack feeds 8 FFMA2
#pragma unroll
                for (int p = 0; p < 8; p++)
                    ffma2(acc[p][DOFF + d], av, w8[p]);
            }
        }
    }
}

__global__ void __launch_bounds__(256, 1)
GeneralLinear_841813590622_kernel(const float* __restrict__ x,
                                  const float* __restrict__ w0,
                                  const float* __restrict__ w1,
                                  const float* __restrict__ w2,
                                  float* __restrict__ out)
{
    extern __shared__ float smem[];
    float* xsb[2] = { smem, smem + XS_BUF };
    float* wsb[2] = { smem + 2 * XS_BUF, smem + 2 * XS_BUF + WS_BUF };
    const float* wl[3] = { w0, w1, w2 };
    const int offs[3] = { 0, 64, 256 };
    const int dims[3] = { 1, 3, 5 };

    const int tid = threadIdx.x;
    const int n0 = blockIdx.x * NROWS;
    const int r = tid >> 3, kg = tid & 7;

    ull acc[8][9];
#pragma unroll
    for (int p = 0; p < 8; p++)
#pragma unroll
        for (int q = 0; q < 9; q++) acc[p][q] = 0ull;

    stage_chunk(x, wl[0], n0, 0, offs[0], dims[0], xsb[0], wsb[0], tid);

    for (int i = 0; i < 48; i++) {
        const int b = i & 1;
        const int nx = i + 1;
        if (nx < 48) {
            const int ln = nx >> 4, cn = nx & 15;
            stage_chunk(x, wl[ln], n0, cn, offs[ln], dims[ln], xsb[nx & 1], wsb[nx & 1], tid);
            asm volatile("cp.async.wait_group 1;" ::: "memory");
        } else {
            asm volatile("cp.async.wait_group 0;" ::: "memory");
        }
        __syncthreads();

        const int l = i >> 4;
        if (l == 0)      compute_chunk<1, 0>(xsb[b], wsb[b], acc, r, kg);
        else if (l == 1) compute_chunk<3, 1>(xsb[b], wsb[b], acc, r, kg);
        else             compute_chunk<5, 4>(xsb[b], wsb[b], acc, r, kg);
        __syncthreads();   // protect buffer b before restaging
    }

    // ---- reduce over kg (lane bits 0..2) via 64-bit butterfly shuffles ----
#pragma unroll
    for (int mask = 1; mask <= 4; mask <<= 1) {
#pragma unroll
        for (int p = 0; p < 8; p++)
#pragma unroll
            for (int q = 0; q < 9; q++) {
                ull o = __shfl_xor_sync(0xffffffffu, acc[p][q], mask);
                acc[p][q] = addf2(acc[p][q], o);
            }
    }

    // ---- kg==0 threads stage the 144 floats of their row to smem (scaled) ----
    const float s = 0.03125f;   // 1/sqrt(1024)
    float* sred = xsb[0];       // free after final sync
    if (kg == 0) {
#pragma unroll
        for (int p = 0; p < 8; p++)
#pragma unroll
            for (int q = 0; q < 9; q++) {
                float lo, hi;
                asm("mov.b64 {%0, %1}, %2;" : "=f"(lo), "=f"(hi) : "l"(acc[p][q]));
                sred[r * 144 + (2 * p) * 9 + q]     = lo * s;
                sred[r * 144 + (2 * p + 1) * 9 + q] = hi * s;
            }
    }
    __syncthreads();

    // ---- cooperative coalesced float4 store: 32 rows * 144 floats = 1152 float4 ----
    const float4* s4 = (const float4*)sred;
    float4* o4 = (float4*)(out + (size_t)n0 * 144);
#pragma unroll
    for (int k = 0; k < 5; k++) {
        int idx = tid + 256 * k;
        if (idx < 1152) o4[idx] = s4[idx];
    }
}

extern "C" void kernel_launch(void* const* d_in, const int* in_sizes, int n_in,
                              void* d_out, int out_size)
{
    const float* x  = (const float*)d_in[0];
    const float* w0 = (const float*)d_in[1];
    const float* w1 = (const float*)d_in[2];
    const float* w2 = (const float*)d_in[3];
    float* out = (float*)d_out;

    cudaFuncSetAttribute(GeneralLinear_841813590622_kernel,
                         cudaFuncAttributeMaxDynamicSharedMemorySize, SMEM_BYTES);
    GeneralLinear_841813590622_kernel<<<256, 256, SMEM_BYTES>>>(x, w0, w1, w2, out);
}